// round 12
// baseline (speedup 1.0000x reference)
#include <cuda_runtime.h>
#include <cstdint>

#define SEQ 4096
#define HID 256
#define EMB 256
#define NEG_LOG2E -1.44269504088896340736f

// ---------------------------------------------------------------------------
// Scratch: x_proj[t][j] pre-scaled by -log2e (4096 x 256 fp32 = 4 MB).
// ---------------------------------------------------------------------------
__device__ float g_xproj[SEQ * HID];

// ---------------------------------------------------------------------------
// Phase 1: x_proj = (embedding[tokens] @ wx_w.T + wx_b) * (-log2e)
// The -log2e pre-scaling lets the recurrence's sigmoid use raw ex2.approx.
// ---------------------------------------------------------------------------
#define TOK_PER_BLK 16

__global__ __launch_bounds__(256) void xproj_kernel(
    const int* __restrict__ tokens,
    const float* __restrict__ embedding,
    const float* __restrict__ wx_w,
    const float* __restrict__ wx_b)
{
    __shared__ float emb_sm[TOK_PER_BLK * EMB];
    const int tid = threadIdx.x;
    const int t0  = blockIdx.x * TOK_PER_BLK;

    #pragma unroll
    for (int i = 0; i < TOK_PER_BLK; i++) {
        long tok = (long)tokens[t0 + i];
        emb_sm[i * EMB + tid] = embedding[tok * (long)EMB + tid];
    }
    __syncthreads();

    float acc[TOK_PER_BLK];
    #pragma unroll
    for (int i = 0; i < TOK_PER_BLK; i++) acc[i] = 0.f;

    const float4* wrow = reinterpret_cast<const float4*>(wx_w + tid * EMB);
    #pragma unroll 4
    for (int k4 = 0; k4 < EMB / 4; k4++) {
        float4 w = wrow[k4];
        #pragma unroll
        for (int i = 0; i < TOK_PER_BLK; i++) {
            float4 e = *reinterpret_cast<const float4*>(&emb_sm[i * EMB + 4 * k4]);
            acc[i] += w.x * e.x + w.y * e.y + w.z * e.z + w.w * e.w;
        }
    }

    const float b = wx_b[tid];
    #pragma unroll
    for (int i = 0; i < TOK_PER_BLK; i++)
        g_xproj[(t0 + i) * HID + tid] = (acc[i] + b) * NEG_LOG2E;
}

// ---------------------------------------------------------------------------
// Phase 2: serial recurrence, 8-CTA cluster (R10 skeleton + chain diet).
//
// CTA r owns h slice [r*32, r*32+32); every dot reads ONLY that slice, so h
// never crosses the cluster — only 1-float partials do. One thread per
// GLOBAL output (o = tid): 16 packed FFMA2 over the slice, arranged as 8
// independent depth-2 chains + packed add2 tree.
//
// All z-contributors (wh_w, wh_b, x_proj) are pre-scaled by -log2e, so the
// accumulated value IS -z*log2e and sigmoid = rcp.approx(1 + ex2.approx(acc))
// — minimal MUFU chain (EX2 16 + FADD 4 + RCP 16).
//
//   sender warp (7 of 8): dot -> one st.shared::cluster into owner's inbox.
//   owner warp (warp 'rank'): dot -> deposit (s + bias' + xp') -> poll full
//   8-slot row (double-pumped 2x16B volatile loads) -> re-arm -> sum8 ->
//   ex2/rcp -> store h -> bar.
// One __syncthreads per step: publishes hbuf[nxt], drains owner's re-arm,
// closes reads of hbuf[cur].
//
// Sentinel protocol (distance-2, proven R8/R10/R11): inbox idles at
// 0xFFFFFFFF (NaN pattern finite dots never produce). Owner re-arms consumed
// words before its end-of-step bar (BAR.SYNC drains STS); senders' t+1 ships
// are after that bar; every other owner consumes them before its t+1 bar;
// their senders' t+2 writes into the re-armed row are causally after that.
// ---------------------------------------------------------------------------
#define NCTA 8
#define THREADS2 256
#define SLICE 32          // outputs (and k's) per CTA
#define SENTB 0xFFFFFFFFu
#define INBOX_WORDS 256   // 32 outputs x 8 sender slots (one buffer)

__device__ __forceinline__ uint32_t smem_u32(const void* p) {
    uint32_t a;
    asm("{ .reg .u64 t; cvta.to.shared.u64 t, %1; cvt.u32.u64 %0, t; }"
        : "=r"(a) : "l"(p));
    return a;
}
__device__ __forceinline__ uint32_t mapa_rank(uint32_t a, uint32_t rank) {
    uint32_t r;
    asm("mapa.shared::cluster.u32 %0, %1, %2;" : "=r"(r) : "r"(a), "r"(rank));
    return r;
}
__device__ __forceinline__ void st_remote_f32(uint32_t a, float v) {
    asm volatile("st.shared::cluster.f32 [%0], %1;" :: "r"(a), "f"(v) : "memory");
}
__device__ __forceinline__ void fma2(unsigned long long& acc,
                                     unsigned long long a, unsigned long long b) {
    asm("fma.rn.f32x2 %0, %1, %2, %0;" : "+l"(acc) : "l"(a), "l"(b));
}
__device__ __forceinline__ void add2(unsigned long long& d,
                                     unsigned long long a, unsigned long long b) {
    asm("add.rn.f32x2 %0, %1, %2;" : "=l"(d) : "l"(a), "l"(b));
}
__device__ __forceinline__ unsigned long long pack2(float x, float y) {
    unsigned long long v;
    asm("mov.b64 %0, {%1, %2};" : "=l"(v) : "f"(x), "f"(y));
    return v;
}
__device__ __forceinline__ void unpack2(unsigned long long v, float& x, float& y) {
    asm("mov.b64 {%0, %1}, %2;" : "=f"(x), "=f"(y) : "l"(v));
}
__device__ __forceinline__ void ldsv4(uint32_t addr, unsigned& a, unsigned& b,
                                      unsigned& c, unsigned& d) {
    asm volatile("ld.volatile.shared.v4.u32 {%0,%1,%2,%3}, [%4];"
                 : "=r"(a), "=r"(b), "=r"(c), "=r"(d) : "r"(addr));
}
__device__ __forceinline__ void stsv4(uint32_t addr, unsigned a, unsigned b,
                                      unsigned c, unsigned d) {
    asm volatile("st.volatile.shared.v4.u32 [%0], {%1,%2,%3,%4};"
                 :: "r"(addr), "r"(a), "r"(b), "r"(c), "r"(d) : "memory");
}
__device__ __forceinline__ void stsv1(uint32_t addr, unsigned v) {
    asm volatile("st.volatile.shared.u32 [%0], %1;"
                 :: "r"(addr), "r"(v) : "memory");
}
// sigmoid tail on pre-scaled acc = -z*log2e : h = 1/(1 + 2^acc)
__device__ __forceinline__ float sigmoid_scaled(float acc) {
    float e, h;
    asm("ex2.approx.f32 %0, %1;" : "=f"(e) : "f"(acc));
    asm("rcp.approx.f32 %0, %1;" : "=f"(h) : "f"(e + 1.0f));
    return h;
}

__global__ __launch_bounds__(THREADS2, 1) __cluster_dims__(NCTA, 1, 1)
void rnn_kernel(const float* __restrict__ wh_w,
                const float* __restrict__ wh_b,
                float* __restrict__ out)
{
    __shared__ __align__(16) float    hbuf[2][SLICE];        // own h slice only
    __shared__ __align__(16) unsigned inbox[2][INBOX_WORDS]; // [o&31][sender]

    const int tid = threadIdx.x;
    uint32_t rank; asm("mov.u32 %0, %%cluster_ctarank;" : "=r"(rank));

    const int o    = tid;            // GLOBAL output index 0..255
    const int own  = o >> 5;         // owner CTA (= warp id) of output o
    const bool owner = (own == (int)rank);

    // Register-resident packed weights, pre-scaled by -log2e
    unsigned long long w[SLICE / 2];
    {
        const float* row = wh_w + o * HID + (int)rank * SLICE;
        #pragma unroll
        for (int i = 0; i < SLICE / 2; i++)
            w[i] = pack2(row[2 * i] * NEG_LOG2E, row[2 * i + 1] * NEG_LOG2E);
    }

    // Init: h0 = 0 (own slice); both inbox buffers armed with sentinel.
    if (tid < SLICE) { hbuf[0][tid] = 0.f; }
    reinterpret_cast<unsigned*>(inbox)[tid]            = SENTB;
    reinterpret_cast<unsigned*>(inbox)[tid + THREADS2] = SENTB;

    float bias = 0.f, bxp = 0.f, hn = 0.f;
    if (owner) {
        bias = wh_b[o] * NEG_LOG2E;
        bxp  = bias + g_xproj[o];          // g_xproj already scaled
    }
    __syncthreads();
    // One-time: all CTAs' sentinels visible before any remote store.
    asm volatile("barrier.cluster.arrive.aligned;" ::: "memory");
    asm volatile("barrier.cluster.wait.aligned;"   ::: "memory");

    // Sender: remote address of owner CTA's inbox slot [buf0][(o&31)*8 + rank]
    uint32_t dst = 0;
    if (!owner)
        dst = mapa_rank(smem_u32(&inbox[0][0]), (uint32_t)own)
            + (uint32_t)(((o & 31) << 3) + (int)rank) * 4u;
    // Owner: local base of its inbox row (32B, 16B-aligned)
    const uint32_t rowbase = smem_u32(&inbox[0][(o & 31) << 3]);
    const uint32_t BUFB = INBOX_WORDS * 4u;   // bytes between inbox buffers

    for (int t = 0; t < SEQ; t++) {
        const int cur = t & 1;
        const int nxt = cur ^ 1;

        float bxp_next = 0.f;
        if (owner && (t + 1 < SEQ))
            bxp_next = bias + __ldg(&g_xproj[(t + 1) * HID + o]);

        // ---- 32-MAC partial: 8 independent depth-2 FFMA2 chains ----
        const ulonglong2* h2 =
            reinterpret_cast<const ulonglong2*>(&hbuf[cur][0]);
        ulonglong2 hv0 = h2[0], hv1 = h2[1], hv2 = h2[2], hv3 = h2[3];
        ulonglong2 hv4 = h2[4], hv5 = h2[5], hv6 = h2[6], hv7 = h2[7];
        unsigned long long a0 = 0ull, a1 = 0ull, a2 = 0ull, a3 = 0ull;
        unsigned long long a4 = 0ull, a5 = 0ull, a6 = 0ull, a7 = 0ull;
        fma2(a0, w[0],  hv0.x); fma2(a0, w[1],  hv0.y);
        fma2(a1, w[2],  hv1.x); fma2(a1, w[3],  hv1.y);
        fma2(a2, w[4],  hv2.x); fma2(a2, w[5],  hv2.y);
        fma2(a3, w[6],  hv3.x); fma2(a3, w[7],  hv3.y);
        fma2(a4, w[8],  hv4.x); fma2(a4, w[9],  hv4.y);
        fma2(a5, w[10], hv5.x); fma2(a5, w[11], hv5.y);
        fma2(a6, w[12], hv6.x); fma2(a6, w[13], hv6.y);
        fma2(a7, w[14], hv7.x); fma2(a7, w[15], hv7.y);
        unsigned long long b0, b1, b2, b3, c0, c1, sp;
        add2(b0, a0, a1); add2(b1, a2, a3);
        add2(b2, a4, a5); add2(b3, a6, a7);
        add2(c0, b0, b1); add2(c1, b2, b3);
        add2(sp, c0, c1);
        float x0, y0;
        unpack2(sp, x0, y0);
        float s = x0 + y0;

        if (!owner) {
            // ship partial straight to the owner CTA
            st_remote_f32(dst + (uint32_t)cur * BUFB, s);
        } else {
            // deposit own partial with bias'+xp' folded in, then poll the row
            const uint32_t rb = rowbase + (uint32_t)cur * BUFB;
            stsv1(rb + (uint32_t)rank * 4u, __float_as_uint(s + bxp));
            unsigned v0, v1, v2, v3, v4, v5, v6, v7;
            for (;;) {
                ldsv4(rb,      v0, v1, v2, v3);
                ldsv4(rb + 16, v4, v5, v6, v7);
                if (v0 != SENTB && v1 != SENTB && v2 != SENTB && v3 != SENTB &&
                    v4 != SENTB && v5 != SENTB && v6 != SENTB && v7 != SENTB)
                    break;
                ldsv4(rb,      v0, v1, v2, v3);         // double-pumped probe
                ldsv4(rb + 16, v4, v5, v6, v7);
                if (v0 != SENTB && v1 != SENTB && v2 != SENTB && v3 != SENTB &&
                    v4 != SENTB && v5 != SENTB && v6 != SENTB && v7 != SENTB)
                    break;
            }
            // re-arm the row for step t+2 (program-ordered before the bar)
            stsv4(rb,      SENTB, SENTB, SENTB, SENTB);
            stsv4(rb + 16, SENTB, SENTB, SENTB, SENTB);

            float z = ((__uint_as_float(v0) + __uint_as_float(v1)) +
                       (__uint_as_float(v2) + __uint_as_float(v3))) +
                      ((__uint_as_float(v4) + __uint_as_float(v5)) +
                       (__uint_as_float(v6) + __uint_as_float(v7)));
            hn = sigmoid_scaled(z);          // z is -z_true*log2e
            hbuf[nxt][o & 31] = hn;
            bxp = bxp_next;
        }
        __syncthreads();  // publish hbuf[nxt]; drain re-arm; reads of [cur] done
    }

    if (owner) out[o] = hn;
}

// ---------------------------------------------------------------------------
// kernel_launch
//   d_in: [0] tokens i32[4096], [1] embedding f32[128000*256],
//         [2] wx_w f32[256*256], [3] wx_b f32[256],
//         [4] wh_w f32[256*256], [5] wh_b f32[256]
// ---------------------------------------------------------------------------
extern "C" void kernel_launch(void* const* d_in, const int* in_sizes, int n_in,
                              void* d_out, int out_size)
{
    const int*   tokens    = (const int*)d_in[0];
    const float* embedding = (const float*)d_in[1];
    const float* wx_w      = (const float*)d_in[2];
    const float* wx_b      = (const float*)d_in[3];
    const float* wh_w      = (const float*)d_in[4];
    const float* wh_b      = (const float*)d_in[5];
    float*       out       = (float*)d_out;

    xproj_kernel<<<SEQ / TOK_PER_BLK, 256>>>(tokens, embedding, wx_w, wx_b);
    rnn_kernel<<<NCTA, THREADS2>>>(wh_w, wh_b, out);
}